// round 4
// baseline (speedup 1.0000x reference)
#include <cuda_runtime.h>
#include <cuda_bf16.h>

#define NN 9216
#define WW 96
#define NB 8192
#define CAP 8

// Dynamic shared layout (total 220160 bytes):
//   [0)      float    sc[9216]          36864
//   [36864)  unsigned hist[8192]        32768  (packed binstart | cnt<<16 after scan)
//   [69632)  ushort   list[8192*8]     131072
//   [200704) unsigned bits[4*384]        6144  (dec1,kept1,dec2,kept2)
//   [206848) unsigned scantmp[1024]      4096
//   [210944) uchar    keepmap[9216]      9216
#define SMEM_BYTES 220160

__device__ __forceinline__ void set_bit(unsigned* arr, int x, int y) {
    int p = x + 2;
    atomicOr(&arr[y * 4 + (p >> 5)], 1u << (p & 31));
}

__global__ void __launch_bounds__(1024, 1) fused_kernel(const float* __restrict__ cls,
                                                        const float* __restrict__ reg,
                                                        float* __restrict__ out) {
    extern __shared__ unsigned char dynsmem[];
    float*          sc      = (float*)dynsmem;
    unsigned*       hist    = (unsigned*)(dynsmem + 36864);
    unsigned short* list    = (unsigned short*)(dynsmem + 69632);
    unsigned*       dec1    = (unsigned*)(dynsmem + 200704);
    unsigned*       kept1   = dec1 + 384;
    unsigned*       dec2    = kept1 + 384;
    unsigned*       kept2   = dec2 + 384;
    unsigned*       scantmp = (unsigned*)(dynsmem + 206848);
    unsigned char*  keepmap = dynsmem + 210944;

    const int t  = threadIdx.x;
    const int tx = t & 31, ty = t >> 5;
    const int x0 = 3 * tx, y0 = 3 * ty;
    const int w  = x0 >> 5, sh = x0 & 31;

    // ---- Phase 0: zero hist + NMS bit arrays ----
    #pragma unroll
    for (int i = 0; i < 8; i++) hist[t * 8 + i] = 0;
    for (int i = t; i < 4 * 384; i += 1024) dec1[i] = 0;
    __syncthreads();

    // ---- Phase 1: load scores, shared histogram + tie lists ----
    // bin = (int)(s*8192) is monotone in s; ties share a bin, resolved
    // exactly in the epilogue by (score, index) comparison.
    #pragma unroll
    for (int k = 0; k < 9; k++) {
        int c = t + k * 1024;
        float s = cls[c];
        sc[c] = s;
        int bin = min((int)(s * 8192.0f), NB - 1);
        unsigned slot = atomicAdd(&hist[bin], 1u);
        if (slot < CAP) list[bin * CAP + slot] = (unsigned short)c;
    }
    __syncthreads();

    // ---- Phase 2: 8192-bin prefix scan -> packed (binstart | cnt<<16) ----
    {
        unsigned v[8], sum = 0;
        #pragma unroll
        for (int i = 0; i < 8; i++) { v[i] = hist[t * 8 + i]; sum += v[i]; }
        scantmp[t] = sum;
        __syncthreads();
        for (int off = 1; off < 1024; off <<= 1) {
            unsigned x = (t >= off) ? scantmp[t - off] : 0u;
            __syncthreads();
            scantmp[t] += x;
            __syncthreads();
        }
        unsigned run = t ? scantmp[t - 1] : 0u;
        #pragma unroll
        for (int i = 0; i < 8; i++) {
            run += v[i];
            hist[t * 8 + i] = (unsigned)(NN - run) | (v[i] << 16);
        }
    }

    // ---- Phase 3: build NMS masks (exact integer geometry, 21x21 boxes) ----
    unsigned m1[9];
    unsigned long long m2all = 0;   // 4 bits/cell: up,left,right,down (thr 0.7)
    unsigned pend = 0;
    #pragma unroll
    for (int k = 0; k < 9; k++) {
        int ry = k / 3, cx = k % 3;
        int x = x0 + cx, y = y0 + ry;
        int c = y * WW + x;
        float s = sc[c];
        unsigned mm1 = 0, n2 = 0;
        if (s > 0.6f) {
            pend |= 1u << k;
            int xm = x % 3, ym = y % 3;
            #define EARLIER(n) (sc[(n)] > s || (sc[(n)] == s && (n) < c))
            if (x > 0  && EARLIER(c - 1))  { mm1 |= 1u << 11; if (xm != 2) n2 |= 2u; }
            if (x < 95 && EARLIER(c + 1))  { mm1 |= 1u << 13; if (xm != 1) n2 |= 4u; }
            if (y > 0  && EARLIER(c - 96)) { mm1 |= 1u << 7;  if (ym != 2) n2 |= 1u; }
            if (y < 95 && EARLIER(c + 96)) { mm1 |= 1u << 17; if (ym != 1) n2 |= 8u; }
            if (x > 1  && xm == 1 && EARLIER(c - 2))   mm1 |= 1u << 10;
            if (x < 94 && xm == 2 && EARLIER(c + 2))   mm1 |= 1u << 14;
            if (y > 1  && ym == 1 && EARLIER(c - 192)) mm1 |= 1u << 2;
            if (y < 94 && ym == 2 && EARLIER(c + 192)) mm1 |= 1u << 22;
            bool sxp4 = (xm == 1), sxm4 = (xm == 2), syp4 = (ym == 1), sym4 = (ym == 2);
            if (x > 0  && y > 0  && !(sxm4 && sym4) && EARLIER(c - 97)) mm1 |= 1u << 6;
            if (x < 95 && y > 0  && !(sxp4 && sym4) && EARLIER(c - 95)) mm1 |= 1u << 8;
            if (x > 0  && y < 95 && !(sxm4 && syp4) && EARLIER(c + 95)) mm1 |= 1u << 16;
            if (x < 95 && y < 95 && !(sxp4 && syp4) && EARLIER(c + 97)) mm1 |= 1u << 18;
            #undef EARLIER
        } else {
            set_bit(dec1, x, y);
            set_bit(dec2, x, y);
        }
        m1[k] = mm1;
        m2all |= (unsigned long long)n2 << (4 * k);
    }
    __syncthreads();   // all init bits visible before anyone spins

    // ---- Phase 4: lock-free monotone fixpoint (both NMS passes) ----
    unsigned p1 = pend, p2 = pend, keep9 = 0;
    while (p1 | p2) {
        bool prog = false;

        if (p1) {
            unsigned dw[7], kw[7];
            #pragma unroll
            for (int r = 0; r < 7; r++) {
                int ry = y0 - 2 + r;
                if ((unsigned)ry < WW) {
                    int base = ry * 4 + w;
                    unsigned dlo = ((volatile unsigned*)dec1)[base];
                    unsigned dhi = ((volatile unsigned*)dec1)[base + 1];
                    unsigned klo = ((volatile unsigned*)kept1)[base];
                    unsigned khi = ((volatile unsigned*)kept1)[base + 1];
                    dw[r] = __funnelshift_r(dlo, dhi, sh) & 0x1FFu;
                    kw[r] = __funnelshift_r(klo, khi, sh) & 0x1FFu;
                } else { dw[r] = 0; kw[r] = 0; }
            }
            #pragma unroll
            for (int k = 0; k < 9; k++) {
                if (!(p1 & (1u << k))) continue;
                int ry = k / 3, cx = k % 3;
                unsigned mm = m1[k], supp = 0, und = 0;
                #pragma unroll
                for (int r = 0; r < 5; r++) {
                    unsigned mrow = (mm >> (5 * r)) & 31u;
                    supp |= mrow & (kw[ry + r] >> cx);
                    und  |= mrow & ((~dw[ry + r]) >> cx);
                }
                if (supp) {
                    int x = x0 + cx, y = y0 + ry;
                    set_bit(dec1, x, y); set_bit(dec2, x, y);
                    dw[ry + 2] |= 1u << (cx + 2);
                    p1 &= ~(1u << k); p2 &= ~(1u << k); prog = true;
                } else if (!und) {
                    int x = x0 + cx, y = y0 + ry;
                    set_bit(dec1, x, y); set_bit(kept1, x, y);
                    dw[ry + 2] |= 1u << (cx + 2);
                    kw[ry + 2] |= 1u << (cx + 2);
                    p1 &= ~(1u << k); prog = true;
                }
            }
        }

        unsigned ready = p2 & ~p1;
        if (ready) {
            unsigned dw[7], kw[7];
            #pragma unroll
            for (int r = 0; r < 7; r++) {
                int ry = y0 - 2 + r;
                if ((unsigned)ry < WW) {
                    int base = ry * 4 + w;
                    unsigned dlo = ((volatile unsigned*)dec2)[base];
                    unsigned dhi = ((volatile unsigned*)dec2)[base + 1];
                    unsigned klo = ((volatile unsigned*)kept2)[base];
                    unsigned khi = ((volatile unsigned*)kept2)[base + 1];
                    dw[r] = __funnelshift_r(dlo, dhi, sh) & 0x1FFu;
                    kw[r] = __funnelshift_r(klo, khi, sh) & 0x1FFu;
                } else { dw[r] = 0; kw[r] = 0; }
            }
            #pragma unroll
            for (int k = 0; k < 9; k++) {
                if (!(ready & (1u << k))) continue;
                int ry = k / 3, cx = k % 3;
                unsigned n2 = (unsigned)(m2all >> (4 * k)) & 15u;
                unsigned supp =
                      ((n2 >> 0) & (kw[ry + 1] >> (cx + 2)))
                    | ((n2 >> 1) & (kw[ry + 2] >> (cx + 1)))
                    | ((n2 >> 2) & (kw[ry + 2] >> (cx + 3)))
                    | ((n2 >> 3) & (kw[ry + 3] >> (cx + 2)));
                unsigned und =
                      ((n2 >> 0) & ((~dw[ry + 1]) >> (cx + 2)))
                    | ((n2 >> 1) & ((~dw[ry + 2]) >> (cx + 1)))
                    | ((n2 >> 2) & ((~dw[ry + 2]) >> (cx + 3)))
                    | ((n2 >> 3) & ((~dw[ry + 3]) >> (cx + 2)));
                if (supp & 1u) {
                    int x = x0 + cx, y = y0 + ry;
                    set_bit(dec2, x, y);
                    p2 &= ~(1u << k); prog = true;
                } else if (!(und & 1u)) {
                    int x = x0 + cx, y = y0 + ry;
                    set_bit(dec2, x, y); set_bit(kept2, x, y);
                    keep9 |= 1u << k;
                    p2 &= ~(1u << k); prog = true;
                }
            }
        }

        if (!prog) __nanosleep(40);
    }

    // Publish keep flags for coalesced epilogue
    #pragma unroll
    for (int k = 0; k < 9; k++) {
        int c = (y0 + k / 3) * WW + x0 + (k % 3);
        keepmap[c] = (keep9 >> k) & 1u;
    }
    __syncthreads();

    // ---- Phase 5: epilogue (rank from shared, regress, scatter) ----
    #pragma unroll
    for (int k = 0; k < 9; k++) {
        int c = t + k * 1024;
        float s = sc[c];
        int bin = min((int)(s * 8192.0f), NB - 1);
        unsigned packed = hist[bin];
        unsigned rank = packed & 0xFFFFu;
        unsigned cnt  = packed >> 16;
        if (cnt <= CAP) {
            for (unsigned j = 0; j < cnt; j++) {
                int idx = (int)list[bin * CAP + j];
                float sj = sc[idx];
                rank += (sj > s) || (sj == s && idx < c);
            }
        } else {            // overflow fallback: exact full recount
            rank = 0;
            for (int j = 0; j < NN; j++) {
                float sj = sc[j];
                rank += (sj > s) || (sj == s && j < c);
            }
        }
        float kq = keepmap[c] ? 1.0f : 0.0f;
        int x = c % WW, y = c / WW;
        float X1 = rintf((2.0f * x) / 0.6f);
        float X2 = rintf((2.0f * x + 12.0f) / 0.6f);
        float Y1 = rintf((2.0f * y) / 0.6f);
        float Y2 = rintf((2.0f * y + 12.0f) / 0.6f);
        float bw = X2 - X1 + 1.0f;
        float bh = Y2 - Y1 + 1.0f;
        float4 d = ((const float4*)reg)[c];
        float* o = out + (int)rank * 5;
        o[0] = (X1 + d.x * bw) * kq;
        o[1] = (Y1 + d.y * bh) * kq;
        o[2] = (X2 + d.z * bw) * kq;
        o[3] = (Y2 + d.w * bh) * kq;
        o[4] = s * kq;
    }
}

extern "C" void kernel_launch(void* const* d_in, const int* in_sizes, int n_in,
                              void* d_out, int out_size) {
    const float* cls = (const float*)d_in[0];
    const float* reg = (const float*)d_in[1];
    if (n_in >= 2 && in_sizes[0] > in_sizes[1]) {   // defensive: metadata order
        const float* t = cls; cls = reg; reg = t;
    }
    float* out = (float*)d_out;

    cudaFuncSetAttribute(fused_kernel,
                         cudaFuncAttributeMaxDynamicSharedMemorySize, SMEM_BYTES);
    fused_kernel<<<1, 1024, SMEM_BYTES>>>(cls, reg, out);
}